// round 3
// baseline (speedup 1.0000x reference)
#include <cuda_runtime.h>
#include <cstdint>

// OneHotEncoder: per-row token histogram (skip pad_idx=0) -> float counts.
// tokens: [B, T] int32, out: [B, 32000] float32.
//
// R3: no shared-memory histogram at all. The 32.8MB output fits in L2
// (DRAM was ~2% in R1/R2), so:
//   (1) cudaMemsetAsync zeroes the output (fast-path, LTS-cap ~2.6us)
//   (2) a fine-grained scatter kernel issues RED.E.ADD.F32 (+1.0f) straight
//       into global for every non-pad token. Integer-valued fp32 sums are
//       exact regardless of order. Random tokens => spread addresses =>
//       ~1.29 cyc/lane REDG, no L2 atomic serialization.
// Column 0 stays zero from the memset because pad tokens are skipped.

constexpr int VOCAB = 32000;
constexpr int NTHREADS = 256;

__global__ __launch_bounds__(NTHREADS, 8)
void onehot_scatter_kernel(const int4* __restrict__ tokens4,
                           float* __restrict__ out,
                           int vecs_per_row)   // T/4
{
    // One int4 (4 tokens) per thread. T divisible by 4 => all 4 tokens of a
    // vector belong to the same row.
    const int g = blockIdx.x * NTHREADS + threadIdx.x;
    const int b = g / vecs_per_row;

    int4 t = tokens4[g];
    float* __restrict__ orow = out + (size_t)b * VOCAB;

    if (t.x != 0) atomicAdd(&orow[t.x], 1.0f);
    if (t.y != 0) atomicAdd(&orow[t.y], 1.0f);
    if (t.z != 0) atomicAdd(&orow[t.z], 1.0f);
    if (t.w != 0) atomicAdd(&orow[t.w], 1.0f);
}

extern "C" void kernel_launch(void* const* d_in, const int* in_sizes, int n_in,
                              void* d_out, int out_size)
{
    const int* tokens = (const int*)d_in[0];   // [B, T] int32
    // d_in[1] = lengths [B] int32 — unused by the reference computation.

    const int B = in_sizes[1];                 // 256
    const int T = in_sizes[0] / B;             // 2048

    float* out = (float*)d_out;                // [B, VOCAB] float32

    // (1) zero the output (capture-safe async memset)
    cudaMemsetAsync(d_out, 0, (size_t)out_size * sizeof(float));

    // (2) scatter-add
    const int total_vecs = (B * T) / 4;        // 131072
    const int blocks = total_vecs / NTHREADS;  // 512
    onehot_scatter_kernel<<<blocks, NTHREADS>>>(
        (const int4*)tokens, out, T / 4);
}

// round 4
// speedup vs baseline: 1.1946x; 1.1946x over previous
#include <cuda_runtime.h>
#include <cstdint>

// OneHotEncoder: per-row token histogram (skip pad_idx=0) -> float counts.
// tokens: [B, T] int32, out: [B, 32000] float32.
//
// R4: f32 smem histogram (counts are integer-valued -> fp32 atomicAdd exact),
// 4-way vocab split (8000 bins = 32KB/CTA, 1024 CTAs, high occupancy,
// balanced), and a single TMA 1-D bulk store (cp.async.bulk) to write each
// 32KB vocab slice smem->global. This removes BOTH the u16->f32 unpack pass
// and the 8000-iteration STG loop from the LSU pipe; the output write is
// offloaded to the TMA engine. Output is written exactly once, coalesced.

constexpr int VOCAB    = 32000;
constexpr int SPLIT    = 4;
constexpr int BINS     = VOCAB / SPLIT;   // 8000 bins = 32000 B f32
constexpr int NTHREADS = 256;

__global__ __launch_bounds__(NTHREADS)
void onehot_hist_tma_kernel(const int4* __restrict__ tokens4,
                            float* __restrict__ out,
                            int vecs_per_row)   // T/4
{
    extern __shared__ float hist[];   // BINS floats = 32000 B

    const int cta = blockIdx.x;
    const int s   = cta & (SPLIT - 1);       // vocab slice index
    const int b   = cta >> 2;                // row index
    const int lo  = s * BINS;
    const int tid = threadIdx.x;

    // Phase 1: zero the slice histogram (float4 stores).
    float4 z = make_float4(0.f, 0.f, 0.f, 0.f);
    #pragma unroll
    for (int i = tid; i < BINS / 4; i += NTHREADS) {
        reinterpret_cast<float4*>(hist)[i] = z;
    }
    __syncthreads();

    // Phase 2: scan the full row, count tokens belonging to this slice.
    // Pad (t==0) excluded explicitly; out-of-slice excluded by unsigned range.
    const int4* __restrict__ trow = tokens4 + (size_t)b * vecs_per_row;
    for (int i = tid; i < vecs_per_row; i += NTHREADS) {
        int4 t = trow[i];
        unsigned x;
        x = (unsigned)(t.x - lo); if (t.x != 0 && x < (unsigned)BINS) atomicAdd(&hist[x], 1.0f);
        x = (unsigned)(t.y - lo); if (t.y != 0 && x < (unsigned)BINS) atomicAdd(&hist[x], 1.0f);
        x = (unsigned)(t.z - lo); if (t.z != 0 && x < (unsigned)BINS) atomicAdd(&hist[x], 1.0f);
        x = (unsigned)(t.w - lo); if (t.w != 0 && x < (unsigned)BINS) atomicAdd(&hist[x], 1.0f);
    }
    __syncthreads();

    // Phase 3: one TMA 1-D bulk store writes the whole 32000B slice.
    if (tid == 0) {
        // Order the generic-proxy smem writes (STS/ATOMS) before the async
        // proxy read. __syncthreads above makes all CTA writes visible here.
        asm volatile("fence.proxy.async.shared::cta;" ::: "memory");
        uint32_t saddr = (uint32_t)__cvta_generic_to_shared(hist);
        float* gdst = out + (size_t)b * VOCAB + lo;   // 16B-aligned (32000B slices)
        asm volatile(
            "cp.async.bulk.global.shared::cta.bulk_group [%0], [%1], %2;"
            :: "l"(gdst), "r"(saddr), "r"((unsigned)(BINS * sizeof(float)))
            : "memory");
        asm volatile("cp.async.bulk.commit_group;" ::: "memory");
        asm volatile("cp.async.bulk.wait_group 0;" ::: "memory");
    }
}

extern "C" void kernel_launch(void* const* d_in, const int* in_sizes, int n_in,
                              void* d_out, int out_size)
{
    const int* tokens = (const int*)d_in[0];   // [B, T] int32
    // d_in[1] = lengths [B] int32 — unused by the reference computation.

    const int B = in_sizes[1];                 // 256
    const int T = in_sizes[0] / B;             // 2048

    float* out = (float*)d_out;                // [B, VOCAB] float32

    const int smem_bytes = BINS * (int)sizeof(float);  // 32000
    cudaFuncSetAttribute(onehot_hist_tma_kernel,
                         cudaFuncAttributeMaxDynamicSharedMemorySize,
                         smem_bytes);

    onehot_hist_tma_kernel<<<B * SPLIT, NTHREADS, smem_bytes>>>(
        (const int4*)tokens, out, T / 4);
}